// round 1
// baseline (speedup 1.0000x reference)
#include <cuda_runtime.h>

// ---------------------------------------------------------------------------
// CVQNN classifier: out[b,w] = log1p(relu(c0[w] + (mx^2+mp^2)/4))
//   mx = sum_k A[k][w]   *x[b,k] + bias[w]
//   mp = sum_k A[k][10+w]*x[b,k] + bias[10+w]
// A/bias/c0 derived from the symplectic parameters by a tiny setup kernel.
// ---------------------------------------------------------------------------

__device__ float g_A[64 * 20];   // A[k][o] = 2*S[rows[o], k],  rows = [0..9, 64..73]
__device__ float g_bias[20];     // d[rows[o]]
__device__ float g_c0[10];       // cov_term[w]/4 - 0.5

// Apply one beamsplitter pass (left-multiply) to a single column held in regs.
template <int START, int COUNT>
__device__ __forceinline__ void bs_apply(float* col,
                                         const float* ct_, const float* st_,
                                         const float* cp_, const float* sp_) {
#pragma unroll
    for (int m = 0; m < COUNT; ++m) {
        const int i = START + 2 * m;
        const int j = i + 1;
        const float ct = ct_[i], st = st_[i], cp = cp_[i], sp = sp_[i];
        const float a = col[i], b = col[j], c = col[64 + i], e = col[64 + j];
        col[i]      = ct * a - cp * st * b - sp * st * e;
        col[j]      = cp * st * a + ct * b - sp * st * c;
        col[64 + i] = sp * st * b + ct * c - cp * st * e;
        col[64 + j] = sp * st * a + cp * st * c + ct * e;
    }
}

__global__ __launch_bounds__(160, 1) void setup_kernel(
    const float* __restrict__ int1_0, const float* __restrict__ sq0,
    const float* __restrict__ int2_0, const float* __restrict__ disp0,
    const float* __restrict__ int1_1, const float* __restrict__ sq1,
    const float* __restrict__ int2_1, const float* __restrict__ disp1) {
    __shared__ float b1ct[63], b1st[63], b1cp[63], b1sp[63];
    __shared__ float b2ct[63], b2st[63], b2cp[63], b2sp[63];
    __shared__ float rc[63], rs[63];
    __shared__ float em[64], ep[64];
    __shared__ float part[128][11];

    const int tid = threadIdx.x;

    // Thread t < 128 owns column t of S (init = identity column).
    // Thread 128 owns the displacement column d (init = 0).
    float col[128];
#pragma unroll
    for (int r = 0; r < 128; ++r) col[r] = 0.0f;
    if (tid < 128) col[tid] = 1.0f;

    const float* i1p[2] = {int1_0, int1_1};
    const float* i2p[2] = {int2_0, int2_1};
    const float* sqp[2] = {sq0, sq1};
    const float* dpp[2] = {disp0, disp1};

    for (int L = 0; L < 2; ++L) {
        const float* i1 = i1p[L];
        const float* i2 = i2p[L];
        const float* sq = sqp[L];
        const float* dsp = dpp[L];

        // Cooperative trig/exp tables for this layer.
        for (int i = tid; i < 63; i += blockDim.x) {
            sincosf(i1[3 * i],     &b1st[i], &b1ct[i]);
            sincosf(i1[3 * i + 1], &b1sp[i], &b1cp[i]);
            sincosf(i2[3 * i],     &b2st[i], &b2ct[i]);
            sincosf(i2[3 * i + 1], &b2sp[i], &b2cp[i]);
            sincosf(i1[3 * i + 2], &rs[i],   &rc[i]);
        }
        for (int i = tid; i < 64; i += blockDim.x) {
            em[i] = expf(-sq[i]);
            ep[i] = expf(sq[i]);
        }
        __syncthreads();

        if (tid < 129) {
            bs_apply<0, 32>(col, b1ct, b1st, b1cp, b1sp);   // bs(int1, start=0)
            bs_apply<1, 31>(col, b1ct, b1st, b1cp, b1sp);   // bs(int1, start=1)
#pragma unroll
            for (int k = 0; k < 63; ++k) {                  // rotation R
                const float c = rc[k], s = rs[k];
                const float a = col[k], b = col[64 + k];
                col[k]      = c * a - s * b;
                col[64 + k] = s * a + c * b;
            }
#pragma unroll
            for (int k = 0; k < 64; ++k) {                  // squeeze
                col[k]      *= em[k];
                col[64 + k] *= ep[k];
            }
            bs_apply<0, 32>(col, b2ct, b2st, b2cp, b2sp);   // bs(int2, start=0)
            bs_apply<1, 31>(col, b2ct, b2st, b2cp, b2sp);   // bs(int2, start=1)
            if (tid == 128) {                               // d[:n] += 2*disp
#pragma unroll
                for (int k = 0; k < 64; ++k) col[k] += 2.0f * dsp[k];
            }
        }
        __syncthreads();  // tables are reused next layer
    }

    // Emit A (k-major, 20 floats per k, 16B-aligned rows).
    if (tid < 64) {
#pragma unroll
        for (int o = 0; o < 20; ++o) {
            const int r = (o < 10) ? o : (54 + o);  // rows[o]
            g_A[tid * 20 + o] = 2.0f * col[r];
        }
    }
    if (tid == 128) {
#pragma unroll
        for (int o = 0; o < 20; ++o) {
            const int r = (o < 10) ? o : (54 + o);
            g_bias[o] = col[r];
        }
    }
    // cov_term[w] = sum over all 128 columns of S[w,t]^2 + S[64+w,t]^2
    if (tid < 128) {
#pragma unroll
        for (int w = 0; w < 10; ++w)
            part[tid][w] = col[w] * col[w] + col[64 + w] * col[64 + w];
    }
    __syncthreads();
    if (tid < 10) {  // deterministic serial reduction (no float atomics)
        float s = 0.0f;
        for (int t = 0; t < 128; ++t) s += part[t][tid];
        g_c0[tid] = 0.25f * s - 0.5f;
    }
}

// ---------------------------------------------------------------------------
// Main kernel: 128 threads/block, 4 elements/thread => 512 rows/block.
// x staged through shared in quarter-row (16-float) chunks for coalescing;
// A read via uniform __ldg (1 L1tex wavefront per LDG.128).
// Shared pitch = 20 floats: conflict-free LDS.128 for both stage and read.
// ---------------------------------------------------------------------------
__global__ __launch_bounds__(128, 3) void cvqnn_main(
    const float* __restrict__ x, float* __restrict__ out, int B) {
    extern __shared__ float sx[];  // [512][20] floats = 40 KB
    const int tid = threadIdx.x;
    const int base = blockIdx.x << 9;  // * 512

    float acc[4][20];
#pragma unroll
    for (int e = 0; e < 4; ++e)
#pragma unroll
        for (int o = 0; o < 20; ++o) acc[e][o] = 0.0f;

    const float4* __restrict__ x4 = reinterpret_cast<const float4*>(x);
    const float4* __restrict__ A4 = reinterpret_cast<const float4*>(g_A);
    float4* s4 = reinterpret_cast<float4*>(sx);

#pragma unroll 1
    for (int qh = 0; qh < 4; ++qh) {  // quarter-rows: k in [16*qh, 16*qh+16)
        // Stage 512 rows x 16 floats, fully coalesced (4 rows x 128B per instr).
#pragma unroll
        for (int it = 0; it < 16; ++it) {
            const int flat = (it << 7) + tid;  // 0..2047
            const int sr = flat >> 2;
            const int q = flat & 3;
            int grow = base + sr;
            if (grow > B - 1) grow = B - 1;  // tail clamp (stores are guarded)
            s4[sr * 5 + q] = x4[grow * 16 + (qh << 2) + q];
        }
        __syncthreads();

#pragma unroll
        for (int kk = 0; kk < 4; ++kk) {
            float4 xv[4];
#pragma unroll
            for (int e = 0; e < 4; ++e)
                xv[e] = s4[(e * 128 + tid) * 5 + kk];
#pragma unroll
            for (int q = 0; q < 4; ++q) {
                const int k = (qh << 4) + (kk << 2) + q;
                float a[20];
#pragma unroll
                for (int j = 0; j < 5; ++j)
                    *reinterpret_cast<float4*>(&a[4 * j]) = __ldg(A4 + k * 5 + j);
#pragma unroll
                for (int e = 0; e < 4; ++e) {
                    const float xk = reinterpret_cast<const float*>(&xv[e])[q];
#pragma unroll
                    for (int o = 0; o < 20; ++o)
                        acc[e][o] = fmaf(a[o], xk, acc[e][o]);
                }
            }
        }
        __syncthreads();
    }

    float bias[20];
#pragma unroll
    for (int o = 0; o < 20; ++o) bias[o] = __ldg(&g_bias[o]);
    float c0[10];
#pragma unroll
    for (int w = 0; w < 10; ++w) c0[w] = __ldg(&g_c0[w]);

#pragma unroll
    for (int e = 0; e < 4; ++e) {
        const int row = base + e * 128 + tid;
        if (row < B) {
            float v[10];
#pragma unroll
            for (int w = 0; w < 10; ++w) {
                const float mx = acc[e][w] + bias[w];
                const float mp = acc[e][10 + w] + bias[10 + w];
                float nm = fmaf(0.25f, mx * mx + mp * mp, c0[w]);
                nm = fmaxf(nm, 0.0f);
                // log1p: cubic series for tiny nm, MUFU log otherwise.
                const float big = __logf(1.0f + nm);
                const float small =
                    nm * fmaf(nm, fmaf(nm, 0.33333333f, -0.5f), 1.0f);
                v[w] = (nm < 0.03125f) ? small : big;
            }
            float2* op = reinterpret_cast<float2*>(out + row * 10);
#pragma unroll
            for (int j = 0; j < 5; ++j)
                op[j] = make_float2(v[2 * j], v[2 * j + 1]);
        }
    }
}

extern "C" void kernel_launch(void* const* d_in, const int* in_sizes, int n_in,
                              void* d_out, int out_size) {
    const float* x = (const float*)d_in[0];
    const int B = in_sizes[0] / 64;

    setup_kernel<<<1, 160>>>((const float*)d_in[1], (const float*)d_in[2],
                             (const float*)d_in[3], (const float*)d_in[4],
                             (const float*)d_in[5], (const float*)d_in[6],
                             (const float*)d_in[7], (const float*)d_in[8]);

    const int grid = (B + 511) >> 9;
    cvqnn_main<<<grid, 128, 512 * 20 * sizeof(float)>>>(x, (float*)d_out, B);
}

// round 2
// speedup vs baseline: 1.2648x; 1.2648x over previous
#include <cuda_runtime.h>
#include <cstdint>

// ---------------------------------------------------------------------------
// CVQNN classifier: out[b,w] = log1p(relu(c0[w] + (mx^2+mp^2)/4))
//   mx = sum_k A[k][w]   *x[b,k] + bias[w]
//   mp = sum_k A[k][10+w]*x[b,k] + bias[10+w]
// Setup kernel builds A/bias/c0 from the symplectic parameters.
// Main kernel: f32x2-packed FMAs (FFMA2), cp.async double-buffered staging.
// ---------------------------------------------------------------------------

__device__ __align__(16) float g_A[64 * 20];   // A[k][o] = 2*S[rows[o], k]
__device__ __align__(16) float g_bias[20];     // d[rows[o]]
__device__ __align__(16) float g_c0[10];       // cov_term[w]/4 - 0.5

// ---------------- f32x2 packed-math helpers (Blackwell FFMA2 path) --------
#define FMA2(acc, a, b) \
    asm("fma.rn.f32x2 %0, %1, %2, %0;" : "+l"(acc) : "l"(a), "l"(b))
#define MUL2(d, a, b) \
    asm("mul.rn.f32x2 %0, %1, %2;" : "=l"(d) : "l"(a), "l"(b))
#define ADD2(d, a, b) \
    asm("add.rn.f32x2 %0, %1, %2;" : "=l"(d) : "l"(a), "l"(b))
#define PACK_DUP(d, f) \
    asm("mov.b64 %0, {%1, %1};" : "=l"(d) : "f"(f))
#define UNPACK2(lo, hi, v) \
    asm("mov.b64 {%0, %1}, %2;" : "=f"(lo), "=f"(hi) : "l"(v))

// ---------------- setup: build S columns in registers ----------------------
template <int START, int COUNT>
__device__ __forceinline__ void bs_apply(float* col,
                                         const float* ct_, const float* st_,
                                         const float* cp_, const float* sp_) {
#pragma unroll
    for (int m = 0; m < COUNT; ++m) {
        const int i = START + 2 * m;
        const int j = i + 1;
        const float ct = ct_[i], st = st_[i], cp = cp_[i], sp = sp_[i];
        const float a = col[i], b = col[j], c = col[64 + i], e = col[64 + j];
        col[i]      = ct * a - cp * st * b - sp * st * e;
        col[j]      = cp * st * a + ct * b - sp * st * c;
        col[64 + i] = sp * st * b + ct * c - cp * st * e;
        col[64 + j] = sp * st * a + cp * st * c + ct * e;
    }
}

__global__ __launch_bounds__(160, 1) void setup_kernel(
    const float* __restrict__ int1_0, const float* __restrict__ sq0,
    const float* __restrict__ int2_0, const float* __restrict__ disp0,
    const float* __restrict__ int1_1, const float* __restrict__ sq1,
    const float* __restrict__ int2_1, const float* __restrict__ disp1) {
    __shared__ float b1ct[63], b1st[63], b1cp[63], b1sp[63];
    __shared__ float b2ct[63], b2st[63], b2cp[63], b2sp[63];
    __shared__ float rc[63], rs[63];
    __shared__ float em[64], ep[64];
    __shared__ float part[128][11];

    const int tid = threadIdx.x;

    float col[128];
#pragma unroll
    for (int r = 0; r < 128; ++r) col[r] = 0.0f;
    if (tid < 128) col[tid] = 1.0f;

    const float* i1p[2] = {int1_0, int1_1};
    const float* i2p[2] = {int2_0, int2_1};
    const float* sqp[2] = {sq0, sq1};
    const float* dpp[2] = {disp0, disp1};

    for (int L = 0; L < 2; ++L) {
        const float* i1 = i1p[L];
        const float* i2 = i2p[L];
        const float* sq = sqp[L];
        const float* dsp = dpp[L];

        for (int i = tid; i < 63; i += blockDim.x) {
            __sincosf(i1[3 * i],     &b1st[i], &b1ct[i]);
            __sincosf(i1[3 * i + 1], &b1sp[i], &b1cp[i]);
            __sincosf(i2[3 * i],     &b2st[i], &b2ct[i]);
            __sincosf(i2[3 * i + 1], &b2sp[i], &b2cp[i]);
            __sincosf(i1[3 * i + 2], &rs[i],   &rc[i]);
        }
        for (int i = tid; i < 64; i += blockDim.x) {
            em[i] = __expf(-sq[i]);
            ep[i] = __expf(sq[i]);
        }
        __syncthreads();

        if (tid < 129) {
            bs_apply<0, 32>(col, b1ct, b1st, b1cp, b1sp);
            bs_apply<1, 31>(col, b1ct, b1st, b1cp, b1sp);
#pragma unroll
            for (int k = 0; k < 63; ++k) {
                const float c = rc[k], s = rs[k];
                const float a = col[k], b = col[64 + k];
                col[k]      = c * a - s * b;
                col[64 + k] = s * a + c * b;
            }
#pragma unroll
            for (int k = 0; k < 64; ++k) {
                col[k]      *= em[k];
                col[64 + k] *= ep[k];
            }
            bs_apply<0, 32>(col, b2ct, b2st, b2cp, b2sp);
            bs_apply<1, 31>(col, b2ct, b2st, b2cp, b2sp);
            if (tid == 128) {
#pragma unroll
                for (int k = 0; k < 64; ++k) col[k] += 2.0f * dsp[k];
            }
        }
        __syncthreads();
    }

    if (tid < 64) {
#pragma unroll
        for (int o = 0; o < 20; ++o) {
            const int r = (o < 10) ? o : (54 + o);
            g_A[tid * 20 + o] = 2.0f * col[r];
        }
    }
    if (tid == 128) {
#pragma unroll
        for (int o = 0; o < 20; ++o) {
            const int r = (o < 10) ? o : (54 + o);
            g_bias[o] = col[r];
        }
    }
    if (tid < 128) {
#pragma unroll
        for (int w = 0; w < 10; ++w)
            part[tid][w] = col[w] * col[w] + col[64 + w] * col[64 + w];
    }
    __syncthreads();
    if (tid < 10) {
        float s = 0.0f;
        for (int t = 0; t < 128; ++t) s += part[t][tid];
        g_c0[tid] = 0.25f * s - 0.5f;
    }
}

// ---------------------------------------------------------------------------
// Main kernel: 128 threads, 2 rows/thread => 256 rows/block.
// x staged via cp.async into a double-buffered [256][20-float-pitch] tile
// (16-float quarter rows), overlapping the next chunk's DRAM fetch with the
// current chunk's FFMA2 work. A read via uniform __ldg (1 wf per LDG.128).
// ---------------------------------------------------------------------------

#define CP_COMMIT() asm volatile("cp.async.commit_group;" ::: "memory")
#define CP_WAIT(N)  asm volatile("cp.async.wait_group %0;" :: "n"(N) : "memory")

// stage quarter-row QH of 256 rows into buffer BUF (8 x 16B per thread)
#define STAGE(QH, BUF)                                                        \
    do {                                                                      \
        _Pragma("unroll")                                                     \
        for (int it = 0; it < 8; ++it) {                                      \
            const int flat = (it << 7) + tid;                                 \
            const int sr = flat >> 2, q = flat & 3;                           \
            int grow = base + sr;                                             \
            if (grow > Bm1) grow = Bm1;                                       \
            const unsigned sa =                                               \
                sbase + (BUF) * 20480u + (unsigned)(sr * 5 + q) * 16u;        \
            const float4* gp = x4 + (size_t)grow * 16 + (QH) * 4 + q;         \
            asm volatile("cp.async.cg.shared.global [%0], [%1], 16;"          \
                         :: "r"(sa), "l"(gp) : "memory");                     \
        }                                                                     \
        CP_COMMIT();                                                          \
    } while (0)

// consume quarter-row QH from buffer BUF: 16 k-values x 2 rows x 10 FFMA2
#define COMPUTE(QH, BUF)                                                      \
    do {                                                                      \
        const float4* s4 =                                                    \
            reinterpret_cast<const float4*>(sx + (BUF) * 5120);               \
        _Pragma("unroll")                                                     \
        for (int kk = 0; kk < 4; ++kk) {                                      \
            const float4 xv0 = s4[tid * 5 + kk];                              \
            const float4 xv1 = s4[(128 + tid) * 5 + kk];                      \
            _Pragma("unroll")                                                 \
            for (int q = 0; q < 4; ++q) {                                     \
                const int k = (QH) * 16 + kk * 4 + q;                         \
                const longlong2* Ap =                                         \
                    reinterpret_cast<const longlong2*>(g_A + k * 20);         \
                long long a[10];                                              \
                _Pragma("unroll")                                             \
                for (int j = 0; j < 5; ++j) {                                 \
                    const longlong2 v = __ldg(Ap + j);                        \
                    a[2 * j] = v.x;                                           \
                    a[2 * j + 1] = v.y;                                       \
                }                                                             \
                const float xk0 = reinterpret_cast<const float*>(&xv0)[q];    \
                const float xk1 = reinterpret_cast<const float*>(&xv1)[q];    \
                long long xx0, xx1;                                           \
                PACK_DUP(xx0, xk0);                                           \
                PACK_DUP(xx1, xk1);                                           \
                _Pragma("unroll")                                             \
                for (int p = 0; p < 10; ++p) {                                \
                    FMA2(acc0[p], a[p], xx0);                                 \
                    FMA2(acc1[p], a[p], xx1);                                 \
                }                                                             \
            }                                                                 \
        }                                                                     \
    } while (0)

__global__ __launch_bounds__(128, 4) void cvqnn_main(
    const float* __restrict__ x, float* __restrict__ out, int B) {
    extern __shared__ float sx[];  // 2 buffers x [256 rows][5 float4] = 40 KB
    const int tid = threadIdx.x;
    const int base = blockIdx.x << 8;  // * 256 rows
    const int Bm1 = B - 1;

    const float4* __restrict__ x4 = reinterpret_cast<const float4*>(x);
    unsigned sbase;
    asm("{ .reg .u64 t; cvta.to.shared.u64 t, %1; cvt.u32.u64 %0, t; }"
        : "=r"(sbase) : "l"(sx));

    // accumulators start at bias (folds the +bias add into the init)
    long long acc0[10], acc1[10];
    {
        const long long* bp = reinterpret_cast<const long long*>(g_bias);
#pragma unroll
        for (int p = 0; p < 10; ++p) {
            const long long b = __ldg(bp + p);
            acc0[p] = b;
            acc1[p] = b;
        }
    }

    // double-buffered pipeline over 4 quarter-rows
    STAGE(0, 0);
    STAGE(1, 1);
    CP_WAIT(1); __syncthreads();
    COMPUTE(0, 0);
    __syncthreads();
    STAGE(2, 0);
    CP_WAIT(1); __syncthreads();
    COMPUTE(1, 1);
    __syncthreads();
    STAGE(3, 1);
    CP_WAIT(1); __syncthreads();
    COMPUTE(2, 0);
    __syncthreads();
    CP_WAIT(0); __syncthreads();
    COMPUTE(3, 1);

    float c0[10];
#pragma unroll
    for (int w = 0; w < 10; ++w) c0[w] = __ldg(&g_c0[w]);

#pragma unroll
    for (int e = 0; e < 2; ++e) {
        const long long* acc = (e == 0) ? acc0 : acc1;
        const int row = base + e * 128 + tid;
        if (row < B) {
            float v[10];
#pragma unroll
            for (int p = 0; p < 5; ++p) {
                // pair p: outputs (2p, 2p+1); acc[p]=mx pair, acc[5+p]=mp pair
                long long t1, t2, s;
                MUL2(t1, acc[p], acc[p]);
                MUL2(t2, acc[5 + p], acc[5 + p]);
                ADD2(s, t1, t2);
                float s0, s1;
                UNPACK2(s0, s1, s);
#pragma unroll
                for (int h = 0; h < 2; ++h) {
                    const int w = 2 * p + h;
                    float nm = fmaf(0.25f, (h == 0) ? s0 : s1, c0[w]);
                    nm = fmaxf(nm, 0.0f);
                    const float big = __logf(1.0f + nm);
                    const float small =
                        nm * fmaf(nm, fmaf(nm, 0.33333333f, -0.5f), 1.0f);
                    v[w] = (nm < 0.03125f) ? small : big;
                }
            }
            float2* op = reinterpret_cast<float2*>(out + (size_t)row * 10);
#pragma unroll
            for (int j = 0; j < 5; ++j)
                op[j] = make_float2(v[2 * j], v[2 * j + 1]);
        }
    }
}

extern "C" void kernel_launch(void* const* d_in, const int* in_sizes, int n_in,
                              void* d_out, int out_size) {
    const float* x = (const float*)d_in[0];
    const int B = in_sizes[0] / 64;

    setup_kernel<<<1, 160>>>((const float*)d_in[1], (const float*)d_in[2],
                             (const float*)d_in[3], (const float*)d_in[4],
                             (const float*)d_in[5], (const float*)d_in[6],
                             (const float*)d_in[7], (const float*)d_in[8]);

    const int grid = (B + 255) >> 8;
    cvqnn_main<<<grid, 128, 2 * 256 * 20 * sizeof(float)>>>(
        x, (float*)d_out, B);
}

// round 3
// speedup vs baseline: 1.7081x; 1.3505x over previous
#include <cuda_runtime.h>
#include <cstdint>

// ---------------------------------------------------------------------------
// CVQNN classifier: out[b,w] = log1p(relu(c0[w] + mx'^2 + mp'^2))
//   mx'[w] = sum_k A[k][w]   *x[b,k] + bias[w]      (A = S[rows,:64], bias=d/2)
//   mp'[w] = sum_k A[k][10+w]*x[b,k] + bias[10+w]
// Setup kernel builds A/bias/c0. Main kernel: 4 rows/thread, f32x2 FFMA2,
// A broadcast from shared, cp.async double-buffered swizzled x staging.
// ---------------------------------------------------------------------------

__device__ __align__(16) float g_A[64 * 20];   // A[k][o] = S[rows[o], k]
__device__ __align__(16) float g_bias[20];     // d[rows[o]] / 2
__device__ __align__(16) float g_c0[10];       // cov_term[w]/4 - 0.5

// ---------------- f32x2 packed-math helpers --------------------------------
#define FMA2(acc, a, b) \
    asm("fma.rn.f32x2 %0, %1, %2, %0;" : "+l"(acc) : "l"(a), "l"(b))
#define MUL2(d, a, b) \
    asm("mul.rn.f32x2 %0, %1, %2;" : "=l"(d) : "l"(a), "l"(b))
#define ADD2(d, a, b) \
    asm("add.rn.f32x2 %0, %1, %2;" : "=l"(d) : "l"(a), "l"(b))
#define PACK_DUP(d, f) \
    asm("mov.b64 %0, {%1, %1};" : "=l"(d) : "f"(f))
#define UNPACK2(lo, hi, v) \
    asm("mov.b64 {%0, %1}, %2;" : "=f"(lo), "=f"(hi) : "l"(v))

// ---------------- setup: build S columns in registers ----------------------
template <int START, int COUNT>
__device__ __forceinline__ void bs_apply(float* col,
                                         const float* ct_, const float* st_,
                                         const float* cp_, const float* sp_) {
#pragma unroll
    for (int m = 0; m < COUNT; ++m) {
        const int i = START + 2 * m;
        const int j = i + 1;
        const float ct = ct_[i], st = st_[i], cp = cp_[i], sp = sp_[i];
        const float a = col[i], b = col[j], c = col[64 + i], e = col[64 + j];
        col[i]      = ct * a - cp * st * b - sp * st * e;
        col[j]      = cp * st * a + ct * b - sp * st * c;
        col[64 + i] = sp * st * b + ct * c - cp * st * e;
        col[64 + j] = sp * st * a + cp * st * c + ct * e;
    }
}

__global__ __launch_bounds__(160, 1) void setup_kernel(
    const float* __restrict__ int1_0, const float* __restrict__ sq0,
    const float* __restrict__ int2_0, const float* __restrict__ disp0,
    const float* __restrict__ int1_1, const float* __restrict__ sq1,
    const float* __restrict__ int2_1, const float* __restrict__ disp1) {
    __shared__ float b1ct[63], b1st[63], b1cp[63], b1sp[63];
    __shared__ float b2ct[63], b2st[63], b2cp[63], b2sp[63];
    __shared__ float rc[63], rs[63];
    __shared__ float em[64], ep[64];
    __shared__ float part[128][11];

    const int tid = threadIdx.x;

    float col[128];
#pragma unroll
    for (int r = 0; r < 128; ++r) col[r] = 0.0f;
    if (tid < 128) col[tid] = 1.0f;

    const float* i1p[2] = {int1_0, int1_1};
    const float* i2p[2] = {int2_0, int2_1};
    const float* sqp[2] = {sq0, sq1};
    const float* dpp[2] = {disp0, disp1};

    for (int L = 0; L < 2; ++L) {
        const float* i1 = i1p[L];
        const float* i2 = i2p[L];
        const float* sq = sqp[L];
        const float* dsp = dpp[L];

        for (int i = tid; i < 63; i += blockDim.x) {
            __sincosf(i1[3 * i],     &b1st[i], &b1ct[i]);
            __sincosf(i1[3 * i + 1], &b1sp[i], &b1cp[i]);
            __sincosf(i2[3 * i],     &b2st[i], &b2ct[i]);
            __sincosf(i2[3 * i + 1], &b2sp[i], &b2cp[i]);
            __sincosf(i1[3 * i + 2], &rs[i],   &rc[i]);
        }
        for (int i = tid; i < 64; i += blockDim.x) {
            em[i] = __expf(-sq[i]);
            ep[i] = __expf(sq[i]);
        }
        __syncthreads();

        if (tid < 129) {
            bs_apply<0, 32>(col, b1ct, b1st, b1cp, b1sp);
            bs_apply<1, 31>(col, b1ct, b1st, b1cp, b1sp);
#pragma unroll
            for (int k = 0; k < 63; ++k) {
                const float c = rc[k], s = rs[k];
                const float a = col[k], b = col[64 + k];
                col[k]      = c * a - s * b;
                col[64 + k] = s * a + c * b;
            }
#pragma unroll
            for (int k = 0; k < 64; ++k) {
                col[k]      *= em[k];
                col[64 + k] *= ep[k];
            }
            bs_apply<0, 32>(col, b2ct, b2st, b2cp, b2sp);
            bs_apply<1, 31>(col, b2ct, b2st, b2cp, b2sp);
            if (tid == 128) {
#pragma unroll
                for (int k = 0; k < 64; ++k) col[k] += 2.0f * dsp[k];
            }
        }
        __syncthreads();
    }

    // A = S[rows, k] (scaling 2 and the 0.25 in nmean folded together)
    if (tid < 64) {
#pragma unroll
        for (int o = 0; o < 20; ++o) {
            const int r = (o < 10) ? o : (54 + o);
            g_A[tid * 20 + o] = col[r];
        }
    }
    if (tid == 128) {
#pragma unroll
        for (int o = 0; o < 20; ++o) {
            const int r = (o < 10) ? o : (54 + o);
            g_bias[o] = 0.5f * col[r];
        }
    }
    if (tid < 128) {
#pragma unroll
        for (int w = 0; w < 10; ++w)
            part[tid][w] = col[w] * col[w] + col[64 + w] * col[64 + w];
    }
    __syncthreads();
    if (tid < 10) {
        float s = 0.0f;
        for (int t = 0; t < 128; ++t) s += part[t][tid];
        g_c0[tid] = 0.25f * s - 0.5f;
    }
}

// ---------------------------------------------------------------------------
// Main kernel: 128 threads, 4 rows/thread => 512 rows/block.
// smem: A (1312 floats incl. pad) + 2 x-buffers of 512 rows x 16 floats,
// XOR-swizzled (q ^= (row>>1)&3) for conflict-free LDS.128 without padding.
// ---------------------------------------------------------------------------

#define A_FLOATS   1312
#define BUF_FLOATS 8192                     // 512 * 16
#define SMEM_BYTES ((A_FLOATS + 2 * BUF_FLOATS) * 4)

#define CP_COMMIT() asm volatile("cp.async.commit_group;" ::: "memory")
#define CP_WAIT(N)  asm volatile("cp.async.wait_group %0;" :: "n"(N) : "memory")

// stage quarter-row QH of 512 rows into buffer BUF (16 x 16B per thread)
#define STAGE(QH, BUF)                                                        \
    do {                                                                      \
        _Pragma("unroll")                                                     \
        for (int it = 0; it < 16; ++it) {                                     \
            const int flat = (it << 7) + tid;                                 \
            const int sr = flat >> 2, q = flat & 3;                           \
            int grow = base + sr;                                             \
            if (grow > Bm1) grow = Bm1;                                       \
            const int f4i = (sr << 2) + (q ^ ((sr >> 1) & 3));                \
            const unsigned sa = sbase + (A_FLOATS * 4u) +                     \
                                (BUF) * (BUF_FLOATS * 4u) + (unsigned)f4i * 16u; \
            const float4* gp = x4 + (size_t)grow * 16 + (QH) * 4 + q;         \
            asm volatile("cp.async.cg.shared.global [%0], [%1], 16;"          \
                         :: "r"(sa), "l"(gp) : "memory");                     \
        }                                                                     \
        CP_COMMIT();                                                          \
    } while (0)

// consume quarter QH from buffer BUF: 16 k x 4 rows x 10 FFMA2
#define COMPUTE(QH, BUF)                                                      \
    do {                                                                      \
        const float4* s4 =                                                    \
            reinterpret_cast<const float4*>(sx + A_FLOATS + (BUF) * BUF_FLOATS); \
        _Pragma("unroll")                                                     \
        for (int kk = 0; kk < 4; ++kk) {                                      \
            float4 xv[4];                                                     \
            _Pragma("unroll")                                                 \
            for (int e = 0; e < 4; ++e)                                       \
                xv[e] = s4[(((e << 7) + tid) << 2) + (kk ^ sw)];              \
            _Pragma("unroll")                                                 \
            for (int q = 0; q < 4; ++q) {                                     \
                const int k = (QH) * 16 + kk * 4 + q;                         \
                const longlong2* Ap =                                         \
                    reinterpret_cast<const longlong2*>(sx + k * 20);          \
                long long a[10];                                              \
                _Pragma("unroll")                                             \
                for (int j = 0; j < 5; ++j) {                                 \
                    const longlong2 v = Ap[j];                                \
                    a[2 * j] = v.x;                                           \
                    a[2 * j + 1] = v.y;                                       \
                }                                                             \
                _Pragma("unroll")                                             \
                for (int e = 0; e < 4; ++e) {                                 \
                    const float xk = reinterpret_cast<const float*>(&xv[e])[q]; \
                    long long xx;                                             \
                    PACK_DUP(xx, xk);                                         \
                    _Pragma("unroll")                                         \
                    for (int p = 0; p < 10; ++p) FMA2(acc[e][p], a[p], xx);   \
                }                                                             \
            }                                                                 \
        }                                                                     \
    } while (0)

__global__ __launch_bounds__(128, 3) void cvqnn_main(
    const float* __restrict__ x, float* __restrict__ out, int B) {
    extern __shared__ float sx[];  // [A 1312f][buf0 8192f][buf1 8192f]
    const int tid = threadIdx.x;
    const int base = blockIdx.x << 9;  // * 512 rows
    const int Bm1 = B - 1;
    const int sw = (tid >> 1) & 3;

    const float4* __restrict__ x4 = reinterpret_cast<const float4*>(x);
    unsigned sbase;
    asm("{ .reg .u64 t; cvta.to.shared.u64 t, %1; cvt.u32.u64 %0, t; }"
        : "=r"(sbase) : "l"(sx));

    // group 0: A -> shared (320 float4, 2.5 per thread)
    {
        const float4* gA4 = reinterpret_cast<const float4*>(g_A);
#pragma unroll
        for (int it = 0; it < 3; ++it) {
            const int i = it * 128 + tid;
            if (i < 320) {
                const unsigned sa = sbase + (unsigned)i * 16u;
                asm volatile("cp.async.cg.shared.global [%0], [%1], 16;"
                             :: "r"(sa), "l"(gA4 + i) : "memory");
            }
        }
        CP_COMMIT();
    }

    // accumulators start at bias
    long long acc[4][10];
    {
        const long long* bp = reinterpret_cast<const long long*>(g_bias);
#pragma unroll
        for (int p = 0; p < 10; ++p) {
            const long long b = __ldg(bp + p);
#pragma unroll
            for (int e = 0; e < 4; ++e) acc[e][p] = b;
        }
    }

    STAGE(0, 0);                      // group 1
    STAGE(1, 1);                      // group 2
    CP_WAIT(1); __syncthreads();      // A + buf0 ready
    COMPUTE(0, 0);
    __syncthreads();
    STAGE(2, 0);                      // group 3
    CP_WAIT(1); __syncthreads();      // buf1 ready
    COMPUTE(1, 1);
    __syncthreads();
    STAGE(3, 1);                      // group 4
    CP_WAIT(1); __syncthreads();      // buf0 ready
    COMPUTE(2, 0);
    __syncthreads();
    CP_WAIT(0); __syncthreads();      // buf1 ready
    COMPUTE(3, 1);

    // epilogue
    long long c0p[5];
    {
        const long long* cp0 = reinterpret_cast<const long long*>(g_c0);
#pragma unroll
        for (int p = 0; p < 5; ++p) c0p[p] = __ldg(cp0 + p);
    }

#pragma unroll
    for (int e = 0; e < 4; ++e) {
        const int row = base + (e << 7) + tid;
        if (row < B) {
            float v[10];
#pragma unroll
            for (int p = 0; p < 5; ++p) {
                long long t1, t2, s;
                MUL2(t1, acc[e][p], acc[e][p]);
                MUL2(t2, acc[e][5 + p], acc[e][5 + p]);
                ADD2(s, t1, t2);
                ADD2(s, s, c0p[p]);
                float s0, s1;
                UNPACK2(s0, s1, s);
#pragma unroll
                for (int h = 0; h < 2; ++h) {
                    float nm = fmaxf((h == 0) ? s0 : s1, 0.0f);
                    const float big = __logf(1.0f + nm);
                    const float small =
                        nm * fmaf(nm, fmaf(nm, 0.33333333f, -0.5f), 1.0f);
                    v[2 * p + h] = (nm < 0.03125f) ? small : big;
                }
            }
            float2* op = reinterpret_cast<float2*>(out + (size_t)row * 10);
#pragma unroll
            for (int j = 0; j < 5; ++j)
                op[j] = make_float2(v[2 * j], v[2 * j + 1]);
        }
    }
}

extern "C" void kernel_launch(void* const* d_in, const int* in_sizes, int n_in,
                              void* d_out, int out_size) {
    const float* x = (const float*)d_in[0];
    const int B = in_sizes[0] / 64;

    static int smem_set = 0;
    if (!smem_set) {
        cudaFuncSetAttribute(cvqnn_main,
                             cudaFuncAttributeMaxDynamicSharedMemorySize,
                             SMEM_BYTES);
        smem_set = 1;
    }

    setup_kernel<<<1, 160>>>((const float*)d_in[1], (const float*)d_in[2],
                             (const float*)d_in[3], (const float*)d_in[4],
                             (const float*)d_in[5], (const float*)d_in[6],
                             (const float*)d_in[7], (const float*)d_in[8]);

    const int grid = (B + 511) >> 9;
    cvqnn_main<<<grid, 128, SMEM_BYTES>>>(x, (float*)d_out, B);
}

// round 4
// speedup vs baseline: 2.0584x; 1.2051x over previous
#include <cuda_runtime.h>
#include <cstdint>

// ---------------------------------------------------------------------------
// CVQNN classifier: out[b,w] = log1p(relu(c0[w] + mx'^2 + mp'^2))
//   mx'[w] = sum_k A[k][w]   *x[b,k] + bias[w]     (A = S[rows,:64], bias=d/2)
//   mp'[w] = sum_k A[k][10+w]*x[b,k] + bias[10+w]
// Single persistent kernel. Block 0 computes A/bias/c0 via row-backward
// propagation (~1.5us) and publishes through a flag; all blocks then run a
// never-draining cp.async pipeline over 512-row tiles with f32x2 FFMA2.
// ---------------------------------------------------------------------------

__device__ __align__(16) float g_A[64 * 20];   // A[k][o] = S[rows[o], k]
__device__ __align__(16) float g_bias[20];     // d[rows[o]] / 2
__device__ __align__(16) float g_c0[10];       // cov_term[w]/4 - 0.5
__device__ volatile int g_flag;                // 0 until first publish

// ---------------- f32x2 packed-math helpers --------------------------------
#define FMA2(acc, a, b) \
    asm("fma.rn.f32x2 %0, %1, %2, %0;" : "+l"(acc) : "l"(a), "l"(b))
#define MUL2(d, a, b) \
    asm("mul.rn.f32x2 %0, %1, %2;" : "=l"(d) : "l"(a), "l"(b))
#define ADD2(d, a, b) \
    asm("add.rn.f32x2 %0, %1, %2;" : "=l"(d) : "l"(a), "l"(b))
#define PACK_DUP(d, f) \
    asm("mov.b64 %0, {%1, %1};" : "=l"(d) : "f"(f))
#define UNPACK2(lo, hi, v) \
    asm("mov.b64 {%0, %1}, %2;" : "=f"(lo), "=f"(hi) : "l"(v))

// ---------------------------------------------------------------------------
// Setup (block 0 only): row-backward propagation.
// v^T <- v^T * F for each factor F of S = M_L1 * M_L0, leftmost factor first.
// Thread t holds element t of all 20 tracked rows. Exchange via shared
// sv[w*132 + t] (pad 132 keeps partner reads conflict-free).
// ---------------------------------------------------------------------------

__device__ __forceinline__ void bs_back(float v[20], float* sv,
                                        const float* p, int start, int tid) {
    const int m = tid & 63;
    const bool lower = tid < 64;
    const bool active = (m >= start) && (m < start + ((start == 0) ? 64 : 62));
#pragma unroll
    for (int w = 0; w < 20; ++w) sv[w * 132 + tid] = v[w];
    __syncthreads();
    if (active) {
        const int rel = m - start;
        const int i = start + (rel & ~1);
        const bool is_i = (rel & 1) == 0;
        float st_, ct_, sp_, cp_;
        __sincosf(p[3 * i], &st_, &ct_);
        __sincosf(p[3 * i + 1], &sp_, &cp_);
        const int o = is_i ? (i + 1) : i;           // partner mode
        const int sameIdx = (lower ? 0 : 64) + o;   // other-mode, same half
        const int crossIdx = (lower ? 64 : 0) + o;  // other-mode, other half
        const float cA1 = (is_i ? cp_ : -cp_) * st_;
        const float cA2 = (lower ? sp_ : -sp_) * st_;
#pragma unroll
        for (int w = 0; w < 20; ++w)
            v[w] = ct_ * v[w] + cA1 * sv[w * 132 + sameIdx]
                              + cA2 * sv[w * 132 + crossIdx];
    }
    __syncthreads();
}

__device__ __forceinline__ void r_back(float v[20], float* sv,
                                       const float* p, int tid) {
    const int k = tid & 63;
    const bool lower = tid < 64;
    float c_ = 1.0f, s_ = 0.0f;
    if (k < 63) __sincosf(p[3 * k + 2], &s_, &c_);
#pragma unroll
    for (int w = 0; w < 20; ++w) sv[w * 132 + tid] = v[w];
    __syncthreads();
    const float cs = lower ? s_ : -s_;
    const int cross = tid ^ 64;
#pragma unroll
    for (int w = 0; w < 20; ++w)
        v[w] = c_ * v[w] + cs * sv[w * 132 + cross];
    __syncthreads();
}

__device__ void run_setup(float* sv,
                          const float* i1_0, const float* sq0,
                          const float* i2_0, const float* d0,
                          const float* i1_1, const float* sq1,
                          const float* i2_1, const float* d1, int tid) {
    const int k = tid & 63;
    const bool lower = tid < 64;
    float v[20];
#pragma unroll
    for (int w = 0; w < 20; ++w) {
        const int r = (w < 10) ? w : (54 + w);  // rows = [0..9, 64..73]
        v[w] = (tid == r) ? 1.0f : 0.0f;
    }
    // ---- layer 1 (second layer; leftmost in S) ----
    bs_back(v, sv, i2_1, 1, tid);
    bs_back(v, sv, i2_1, 0, tid);
    {
        const float e = lower ? __expf(-sq1[k]) : __expf(sq1[k]);
#pragma unroll
        for (int w = 0; w < 20; ++w) v[w] *= e;
    }
    r_back(v, sv, i1_1, tid);
    bs_back(v, sv, i1_1, 1, tid);
    bs_back(v, sv, i1_1, 0, tid);
    // capture dot0 = row_r(M_L1) . [2*disp0; 0]   (d = M_L1*s0 + s1)
#pragma unroll
    for (int w = 0; w < 20; ++w)
        sv[w * 132 + tid] = lower ? v[w] * 2.0f * d0[tid] : 0.0f;
    __syncthreads();
    if (tid < 20) {
        float s = 0.0f;
        for (int t = 0; t < 64; ++t) s += sv[tid * 132 + t];
        sv[2640 + tid] = s;  // scratch just past exchange region (max 2635)
    }
    __syncthreads();
    // ---- layer 0 ----
    bs_back(v, sv, i2_0, 1, tid);
    bs_back(v, sv, i2_0, 0, tid);
    {
        const float e = lower ? __expf(-sq0[k]) : __expf(sq0[k]);
#pragma unroll
        for (int w = 0; w < 20; ++w) v[w] *= e;
    }
    r_back(v, sv, i1_0, tid);
    bs_back(v, sv, i1_0, 1, tid);
    bs_back(v, sv, i1_0, 0, tid);
    // ---- outputs ----
    if (lower) {
#pragma unroll
        for (int o = 0; o < 20; ++o) g_A[tid * 20 + o] = v[o];  // A[k][o]=S[r,k]
    }
#pragma unroll
    for (int w = 0; w < 10; ++w)
        sv[w * 132 + tid] = v[w] * v[w] + v[w + 10] * v[w + 10];
    __syncthreads();
    if (tid < 10) {
        float s = 0.0f;
        for (int t = 0; t < 128; ++t) s += sv[tid * 132 + t];
        g_c0[tid] = 0.25f * s - 0.5f;
    }
    if (tid < 20) {
        float b = 0.5f * sv[2640 + tid];
        if (tid < 10) b += d1[tid];  // + 2*disp1[r], halved
        g_bias[tid] = b;
    }
    __syncthreads();
    __threadfence();
    if (tid == 0) g_flag = 1;
}

// ---------------------------------------------------------------------------
// Main pipeline: 128 threads, 512 rows/tile, persistent over tiles.
// smem: A (1312 floats) + 2 x-buffers of 512 rows x 16 floats, XOR-swizzled.
// ---------------------------------------------------------------------------

#define A_FLOATS   1312
#define BUF_FLOATS 8192                       // 512 * 16
#define SMEM_BYTES ((A_FLOATS + 2 * BUF_FLOATS) * 4)

#define CP_COMMIT() asm volatile("cp.async.commit_group;" ::: "memory")
#define CP_WAIT(N)  asm volatile("cp.async.wait_group %0;" :: "n"(N) : "memory")

#define STAGE(ROWBASE, QH, BUF)                                               \
    do {                                                                      \
        _Pragma("unroll")                                                     \
        for (int it = 0; it < 16; ++it) {                                     \
            const int flat = (it << 7) + tid;                                 \
            const int sr = flat >> 2, q = flat & 3;                           \
            int grow = (ROWBASE) + sr;                                        \
            if (grow > Bm1) grow = Bm1;                                       \
            const int f4i = (sr << 2) + (q ^ ((sr >> 1) & 3));                \
            const unsigned sa = sbase + (A_FLOATS * 4u) +                     \
                                (BUF) * (BUF_FLOATS * 4u) + (unsigned)f4i * 16u; \
            const float4* gp = x4 + (size_t)grow * 16 + (QH) * 4 + q;         \
            asm volatile("cp.async.cg.shared.global [%0], [%1], 16;"          \
                         :: "r"(sa), "l"(gp) : "memory");                     \
        }                                                                     \
        CP_COMMIT();                                                          \
    } while (0)

#define COMPUTE(QH, BUF)                                                      \
    do {                                                                      \
        const float4* s4 =                                                    \
            reinterpret_cast<const float4*>(sx + A_FLOATS + (BUF) * BUF_FLOATS); \
        _Pragma("unroll")                                                     \
        for (int kk = 0; kk < 4; ++kk) {                                      \
            float4 xv[4];                                                     \
            _Pragma("unroll")                                                 \
            for (int e = 0; e < 4; ++e)                                       \
                xv[e] = s4[(((e << 7) + tid) << 2) + (kk ^ sw)];              \
            _Pragma("unroll")                                                 \
            for (int q = 0; q < 4; ++q) {                                     \
                const int k = (QH) * 16 + kk * 4 + q;                         \
                const longlong2* Ap =                                         \
                    reinterpret_cast<const longlong2*>(sx + k * 20);          \
                long long a[10];                                              \
                _Pragma("unroll")                                             \
                for (int j = 0; j < 5; ++j) {                                 \
                    const longlong2 vv = Ap[j];                               \
                    a[2 * j] = vv.x;                                          \
                    a[2 * j + 1] = vv.y;                                      \
                }                                                             \
                _Pragma("unroll")                                             \
                for (int e = 0; e < 4; ++e) {                                 \
                    const float xk = reinterpret_cast<const float*>(&xv[e])[q]; \
                    long long xx;                                             \
                    PACK_DUP(xx, xk);                                         \
                    _Pragma("unroll")                                         \
                    for (int p = 0; p < 10; ++p) FMA2(acc[e][p], a[p], xx);   \
                }                                                             \
            }                                                                 \
        }                                                                     \
    } while (0)

__global__ __launch_bounds__(128, 3) void cvqnn_main(
    const float* __restrict__ x, float* __restrict__ out, int B, int ntiles,
    const float* __restrict__ i1_0, const float* __restrict__ sq0,
    const float* __restrict__ i2_0, const float* __restrict__ d0,
    const float* __restrict__ i1_1, const float* __restrict__ sq1,
    const float* __restrict__ i2_1, const float* __restrict__ d1) {
    extern __shared__ float sx[];  // [A 1312f][buf0 8192f][buf1 8192f]
    const int tid = threadIdx.x;
    const int G = gridDim.x;
    const int Bm1 = B - 1;
    const int sw = (tid >> 1) & 3;

    const float4* __restrict__ x4 = reinterpret_cast<const float4*>(x);
    unsigned sbase;
    asm("{ .reg .u64 t; cvta.to.shared.u64 t, %1; cvt.u32.u64 %0, t; }"
        : "=r"(sbase) : "l"(sx));

    if (blockIdx.x == 0) {
        run_setup(sx, i1_0, sq0, i2_0, d0, i1_1, sq1, i2_1, d1, tid);
    } else {
        if (tid == 0)
            while (g_flag == 0) __nanosleep(64);
        __syncthreads();
        __threadfence();
    }

    // group 1: A -> shared (320 float4)
    {
        const float4* gA4 = reinterpret_cast<const float4*>(g_A);
#pragma unroll
        for (int it = 0; it < 3; ++it) {
            const int i = it * 128 + tid;
            if (i < 320) {
                const unsigned sa = sbase + (unsigned)i * 16u;
                asm volatile("cp.async.cg.shared.global [%0], [%1], 16;"
                             :: "r"(sa), "l"(gA4 + i) : "memory");
            }
        }
        CP_COMMIT();
    }

    int tile = blockIdx.x;
    int base = tile << 9;
    STAGE(base, 0, 0);  // group 2
    STAGE(base, 1, 1);  // group 3

    const long long* bp = reinterpret_cast<const long long*>(g_bias);
    const long long* cp0 = reinterpret_cast<const long long*>(g_c0);

    while (true) {
        long long acc[4][10];
#pragma unroll
        for (int p = 0; p < 10; ++p) {
            const long long b = __ldg(bp + p);
#pragma unroll
            for (int e = 0; e < 4; ++e) acc[e][p] = b;
        }
        const bool more = (tile + G) < ntiles;
        const int nbase = (tile + G) << 9;

        CP_WAIT(1); __syncthreads();        // A + q0 landed
        COMPUTE(0, 0); __syncthreads();
        STAGE(base, 2, 0);
        CP_WAIT(1); __syncthreads();        // q1 landed
        COMPUTE(1, 1); __syncthreads();
        STAGE(base, 3, 1);
        CP_WAIT(1); __syncthreads();        // q2 landed
        COMPUTE(2, 0); __syncthreads();
        if (more) { STAGE(nbase, 0, 0); CP_WAIT(1); }
        else      { CP_WAIT(0); }
        __syncthreads();                    // q3 landed
        COMPUTE(3, 1); __syncthreads();
        if (more) STAGE(nbase, 1, 1);       // overlaps epilogue

        // epilogue
        long long c0p[5];
#pragma unroll
        for (int p = 0; p < 5; ++p) c0p[p] = __ldg(cp0 + p);
#pragma unroll
        for (int e = 0; e < 4; ++e) {
            const int row = base + (e << 7) + tid;
            if (row < B) {
                float v[10];
#pragma unroll
                for (int p = 0; p < 5; ++p) {
                    long long t1, t2, s;
                    MUL2(t1, acc[e][p], acc[e][p]);
                    MUL2(t2, acc[e][5 + p], acc[e][5 + p]);
                    ADD2(s, t1, t2);
                    ADD2(s, s, c0p[p]);
                    float s0, s1;
                    UNPACK2(s0, s1, s);
#pragma unroll
                    for (int h = 0; h < 2; ++h) {
                        float nm = fmaxf((h == 0) ? s0 : s1, 0.0f);
                        const float big = __logf(1.0f + nm);
                        const float small =
                            nm * fmaf(nm, fmaf(nm, 0.33333333f, -0.5f), 1.0f);
                        v[2 * p + h] = (nm < 0.03125f) ? small : big;
                    }
                }
                float2* op = reinterpret_cast<float2*>(out + (size_t)row * 10);
#pragma unroll
                for (int j = 0; j < 5; ++j)
                    op[j] = make_float2(v[2 * j], v[2 * j + 1]);
            }
        }

        if (!more) break;
        tile += G;
        base = nbase;
    }
}

extern "C" void kernel_launch(void* const* d_in, const int* in_sizes, int n_in,
                              void* d_out, int out_size) {
    const float* x = (const float*)d_in[0];
    const int B = in_sizes[0] / 64;
    const int ntiles = (B + 511) >> 9;

    cudaFuncSetAttribute(cvqnn_main,
                         cudaFuncAttributeMaxDynamicSharedMemorySize,
                         SMEM_BYTES);

    const int grid = (ntiles < 444) ? ntiles : 444;  // 148 SMs x 3 blocks
    cvqnn_main<<<grid, 128, SMEM_BYTES>>>(
        x, (float*)d_out, B, ntiles,
        (const float*)d_in[1], (const float*)d_in[2],
        (const float*)d_in[3], (const float*)d_in[4],
        (const float*)d_in[5], (const float*)d_in[6],
        (const float*)d_in[7], (const float*)d_in[8]);
}

// round 5
// speedup vs baseline: 2.0643x; 1.0029x over previous
#include <cuda_runtime.h>
#include <cstdint>

// ---------------------------------------------------------------------------
// CVQNN classifier: out[b,w] = log1p(relu(c0[w] + mx'^2 + mp'^2))
//   mx'[w] = sum_k A[k][w]   *x[b,k] + bias[w]     (A = S[rows,:64], bias=d/2)
//   mp'[w] = sum_k A[k][10+w]*x[b,k] + bias[10+w]
// Single persistent kernel. Block 0 computes A/bias/c0 (row-backward
// propagation) and publishes via flag. Each WARP then runs an independent
// double-buffered cp.async pipeline over its private 128-row slab of each
// 512-row tile: no inter-warp barriers in the steady state.
// ---------------------------------------------------------------------------

__device__ __align__(16) float g_A[64 * 20];   // A[k][o] = S[rows[o], k]
__device__ __align__(16) float g_bias[20];     // d[rows[o]] / 2
__device__ __align__(16) float g_c0[10];       // cov_term[w]/4 - 0.5
__device__ volatile int g_flag;                // 0 until first publish

// ---------------- f32x2 packed-math helpers --------------------------------
#define FMA2(acc, a, b) \
    asm("fma.rn.f32x2 %0, %1, %2, %0;" : "+l"(acc) : "l"(a), "l"(b))
#define MUL2(d, a, b) \
    asm("mul.rn.f32x2 %0, %1, %2;" : "=l"(d) : "l"(a), "l"(b))
#define ADD2(d, a, b) \
    asm("add.rn.f32x2 %0, %1, %2;" : "=l"(d) : "l"(a), "l"(b))
#define PACK_DUP(d, f) \
    asm("mov.b64 %0, {%1, %1};" : "=l"(d) : "f"(f))
#define UNPACK2(lo, hi, v) \
    asm("mov.b64 {%0, %1}, %2;" : "=f"(lo), "=f"(hi) : "l"(v))

// ---------------------------------------------------------------------------
// Setup (block 0 only): row-backward propagation, v^T <- v^T * F.
// Thread t holds element t of all 20 tracked rows; exchange via shared.
// ---------------------------------------------------------------------------

__device__ __forceinline__ void bs_back(float v[20], float* sv,
                                        const float* p, int start, int tid) {
    const int m = tid & 63;
    const bool lower = tid < 64;
    const bool active = (m >= start) && (m < start + ((start == 0) ? 64 : 62));
#pragma unroll
    for (int w = 0; w < 20; ++w) sv[w * 132 + tid] = v[w];
    __syncthreads();
    if (active) {
        const int rel = m - start;
        const int i = start + (rel & ~1);
        const bool is_i = (rel & 1) == 0;
        float st_, ct_, sp_, cp_;
        __sincosf(p[3 * i], &st_, &ct_);
        __sincosf(p[3 * i + 1], &sp_, &cp_);
        const int o = is_i ? (i + 1) : i;
        const int sameIdx = (lower ? 0 : 64) + o;
        const int crossIdx = (lower ? 64 : 0) + o;
        const float cA1 = (is_i ? cp_ : -cp_) * st_;
        const float cA2 = (lower ? sp_ : -sp_) * st_;
#pragma unroll
        for (int w = 0; w < 20; ++w)
            v[w] = ct_ * v[w] + cA1 * sv[w * 132 + sameIdx]
                              + cA2 * sv[w * 132 + crossIdx];
    }
    __syncthreads();
}

__device__ __forceinline__ void r_back(float v[20], float* sv,
                                       const float* p, int tid) {
    const int k = tid & 63;
    const bool lower = tid < 64;
    float c_ = 1.0f, s_ = 0.0f;
    if (k < 63) __sincosf(p[3 * k + 2], &s_, &c_);
#pragma unroll
    for (int w = 0; w < 20; ++w) sv[w * 132 + tid] = v[w];
    __syncthreads();
    const float cs = lower ? s_ : -s_;
    const int cross = tid ^ 64;
#pragma unroll
    for (int w = 0; w < 20; ++w)
        v[w] = c_ * v[w] + cs * sv[w * 132 + cross];
    __syncthreads();
}

__device__ void run_setup(float* sv,
                          const float* i1_0, const float* sq0,
                          const float* i2_0, const float* d0,
                          const float* i1_1, const float* sq1,
                          const float* i2_1, const float* d1, int tid) {
    const int k = tid & 63;
    const bool lower = tid < 64;
    float v[20];
#pragma unroll
    for (int w = 0; w < 20; ++w) {
        const int r = (w < 10) ? w : (54 + w);  // rows = [0..9, 64..73]
        v[w] = (tid == r) ? 1.0f : 0.0f;
    }
    // ---- layer 1 (leftmost in S) ----
    bs_back(v, sv, i2_1, 1, tid);
    bs_back(v, sv, i2_1, 0, tid);
    {
        const float e = lower ? __expf(-sq1[k]) : __expf(sq1[k]);
#pragma unroll
        for (int w = 0; w < 20; ++w) v[w] *= e;
    }
    r_back(v, sv, i1_1, tid);
    bs_back(v, sv, i1_1, 1, tid);
    bs_back(v, sv, i1_1, 0, tid);
    // dot0 = row_r(M_L1) . [2*disp0; 0]
#pragma unroll
    for (int w = 0; w < 20; ++w)
        sv[w * 132 + tid] = lower ? v[w] * 2.0f * d0[tid] : 0.0f;
    __syncthreads();
    if (tid < 20) {
        float s = 0.0f;
        for (int t = 0; t < 64; ++t) s += sv[tid * 132 + t];
        sv[2640 + tid] = s;
    }
    __syncthreads();
    // ---- layer 0 ----
    bs_back(v, sv, i2_0, 1, tid);
    bs_back(v, sv, i2_0, 0, tid);
    {
        const float e = lower ? __expf(-sq0[k]) : __expf(sq0[k]);
#pragma unroll
        for (int w = 0; w < 20; ++w) v[w] *= e;
    }
    r_back(v, sv, i1_0, tid);
    bs_back(v, sv, i1_0, 1, tid);
    bs_back(v, sv, i1_0, 0, tid);
    // ---- outputs ----
    if (lower) {
#pragma unroll
        for (int o = 0; o < 20; ++o) g_A[tid * 20 + o] = v[o];
    }
#pragma unroll
    for (int w = 0; w < 10; ++w)
        sv[w * 132 + tid] = v[w] * v[w] + v[w + 10] * v[w + 10];
    __syncthreads();
    if (tid < 10) {
        float s = 0.0f;
        for (int t = 0; t < 128; ++t) s += sv[tid * 132 + t];
        g_c0[tid] = 0.25f * s - 0.5f;
    }
    if (tid < 20) {
        float b = 0.5f * sv[2640 + tid];
        if (tid < 10) b += d1[tid];
        g_bias[tid] = b;
    }
    __syncthreads();
    __threadfence();
    if (tid == 0) g_flag = 1;
}

// ---------------------------------------------------------------------------
// Main: 128 threads = 4 independent warp-pipelines, 512 rows/tile.
// smem: A (1312 floats) + per-warp [2 x 128 rows x 16 floats] buffers.
// ---------------------------------------------------------------------------

#define A_FLOATS    1312
#define QBUF_FLOATS 2048                    // 128 rows * 16 floats
#define WBUF_FLOATS (2 * QBUF_FLOATS)
#define SMEM_BYTES  ((A_FLOATS + 4 * WBUF_FLOATS) * 4)

#define CP_COMMIT() asm volatile("cp.async.commit_group;" ::: "memory")
#define CP_WAIT(N)  asm volatile("cp.async.wait_group %0;" :: "n"(N) : "memory")
#define SYNCW()     __syncwarp()

// stage quarter-row QH of this warp's 128-row slab (base SLAB) into BUF
#define STAGEW(SLAB, QH, BUF)                                                 \
    do {                                                                      \
        _Pragma("unroll")                                                     \
        for (int it = 0; it < 16; ++it) {                                     \
            const int flat = (it << 5) + lane;                                \
            const int sr = flat >> 2, q = flat & 3;                           \
            int grow = (SLAB) + sr;                                           \
            if (grow > Bm1) grow = Bm1;                                       \
            const int f4i = (sr << 2) + (q ^ ((sr >> 1) & 3));                \
            const unsigned sa = warpbase +                                    \
                                (BUF) * (QBUF_FLOATS * 4u) + (unsigned)f4i * 16u; \
            const float4* gp = x4 + (size_t)grow * 16 + (QH) * 4 + q;         \
            asm volatile("cp.async.cg.shared.global [%0], [%1], 16;"          \
                         :: "r"(sa), "l"(gp) : "memory");                     \
        }                                                                     \
        CP_COMMIT();                                                          \
    } while (0)

// consume quarter QH from BUF: 16 k x 4 rows x 10 FFMA2
#define COMPUTEW(QH, BUF)                                                     \
    do {                                                                      \
        const float4* s4 = reinterpret_cast<const float4*>(                   \
            sx + A_FLOATS + wid * WBUF_FLOATS + (BUF) * QBUF_FLOATS);         \
        _Pragma("unroll")                                                     \
        for (int kk = 0; kk < 4; ++kk) {                                      \
            float4 xv[4];                                                     \
            _Pragma("unroll")                                                 \
            for (int e = 0; e < 4; ++e)                                       \
                xv[e] = s4[(((e << 5) + lane) << 2) + (kk ^ sw)];             \
            _Pragma("unroll")                                                 \
            for (int q = 0; q < 4; ++q) {                                     \
                const int k = (QH) * 16 + kk * 4 + q;                         \
                const longlong2* Ap =                                         \
                    reinterpret_cast<const longlong2*>(sx + k * 20);          \
                long long a[10];                                              \
                _Pragma("unroll")                                             \
                for (int j = 0; j < 5; ++j) {                                 \
                    const longlong2 vv = Ap[j];                               \
                    a[2 * j] = vv.x;                                          \
                    a[2 * j + 1] = vv.y;                                      \
                }                                                             \
                _Pragma("unroll")                                             \
                for (int e = 0; e < 4; ++e) {                                 \
                    const float xk = reinterpret_cast<const float*>(&xv[e])[q]; \
                    long long xx;                                             \
                    PACK_DUP(xx, xk);                                         \
                    _Pragma("unroll")                                         \
                    for (int p = 0; p < 10; ++p) FMA2(acc[e][p], a[p], xx);   \
                }                                                             \
            }                                                                 \
        }                                                                     \
    } while (0)

__global__ __launch_bounds__(128, 3) void cvqnn_main(
    const float* __restrict__ x, float* __restrict__ out, int B, int ntiles,
    const float* __restrict__ i1_0, const float* __restrict__ sq0,
    const float* __restrict__ i2_0, const float* __restrict__ d0,
    const float* __restrict__ i1_1, const float* __restrict__ sq1,
    const float* __restrict__ i2_1, const float* __restrict__ d1) {
    extern __shared__ float sx[];  // [A 1312f][warp0 2x2048f]...[warp3]
    const int tid = threadIdx.x;
    const int lane = tid & 31;
    const int wid = tid >> 5;
    const int G = gridDim.x;
    const int Bm1 = B - 1;
    const int sw = (lane >> 1) & 3;

    const float4* __restrict__ x4 = reinterpret_cast<const float4*>(x);
    unsigned sbase;
    asm("{ .reg .u64 t; cvta.to.shared.u64 t, %1; cvt.u32.u64 %0, t; }"
        : "=r"(sbase) : "l"(sx));
    const unsigned warpbase =
        sbase + A_FLOATS * 4u + (unsigned)wid * (WBUF_FLOATS * 4u);

    if (blockIdx.x == 0) {
        run_setup(sx, i1_0, sq0, i2_0, d0, i1_1, sq1, i2_1, d1, tid);
    } else {
        if (tid == 0)
            while (g_flag == 0) __nanosleep(64);
        __syncthreads();
        __threadfence();
    }
    __syncthreads();  // setup scratch reuse of sx is done

    // group 1 (per thread): A -> shared (320 float4, all threads cooperate)
    {
        const float4* gA4 = reinterpret_cast<const float4*>(g_A);
#pragma unroll
        for (int it = 0; it < 3; ++it) {
            const int i = it * 128 + tid;
            if (i < 320) {
                const unsigned sa = sbase + (unsigned)i * 16u;
                asm volatile("cp.async.cg.shared.global [%0], [%1], 16;"
                             :: "r"(sa), "l"(gA4 + i) : "memory");
            }
        }
        CP_COMMIT();
    }

    int tile = blockIdx.x;
    int slab = (tile << 9) + (wid << 7);  // this warp's 128-row slab
    STAGEW(slab, 0, 0);                   // group 2
    STAGEW(slab, 1, 1);                   // group 3
    CP_WAIT(2);        // A (oldest group) complete for every thread
    __syncthreads();   // A visible block-wide; last block barrier

    const long long* bp = reinterpret_cast<const long long*>(g_bias);
    const long long* cp0 = reinterpret_cast<const long long*>(g_c0);

    while (true) {
        long long acc[4][10];
#pragma unroll
        for (int p = 0; p < 10; ++p) {
            const long long b = __ldg(bp + p);
#pragma unroll
            for (int e = 0; e < 4; ++e) acc[e][p] = b;
        }
        const bool more = (tile + G) < ntiles;
        const int nslab = ((tile + G) << 9) + (wid << 7);

        CP_WAIT(1); SYNCW();
        COMPUTEW(0, 0); SYNCW();
        STAGEW(slab, 2, 0);
        CP_WAIT(1); SYNCW();
        COMPUTEW(1, 1); SYNCW();
        STAGEW(slab, 3, 1);
        CP_WAIT(1); SYNCW();
        COMPUTEW(2, 0); SYNCW();
        if (more) { STAGEW(nslab, 0, 0); CP_WAIT(1); }
        else      { CP_WAIT(0); }
        SYNCW();
        COMPUTEW(3, 1); SYNCW();
        if (more) STAGEW(nslab, 1, 1);  // overlaps epilogue

        // epilogue (register-only inputs; stores overlap next tile's fetch)
        long long c0p[5];
#pragma unroll
        for (int p = 0; p < 5; ++p) c0p[p] = __ldg(cp0 + p);
#pragma unroll
        for (int e = 0; e < 4; ++e) {
            const int row = slab + (e << 5) + lane;
            if (row < B) {
                float v[10];
#pragma unroll
                for (int p = 0; p < 5; ++p) {
                    long long t1, t2, s;
                    MUL2(t1, acc[e][p], acc[e][p]);
                    MUL2(t2, acc[e][5 + p], acc[e][5 + p]);
                    ADD2(s, t1, t2);
                    ADD2(s, s, c0p[p]);
                    float s0, s1;
                    UNPACK2(s0, s1, s);
#pragma unroll
                    for (int h = 0; h < 2; ++h) {
                        float nm = fmaxf((h == 0) ? s0 : s1, 0.0f);
                        const float big = __logf(1.0f + nm);
                        const float small =
                            nm * fmaf(nm, fmaf(nm, 0.33333333f, -0.5f), 1.0f);
                        v[2 * p + h] = (nm < 0.03125f) ? small : big;
                    }
                }
                float2* op = reinterpret_cast<float2*>(out + (size_t)row * 10);
#pragma unroll
                for (int j = 0; j < 5; ++j)
                    op[j] = make_float2(v[2 * j], v[2 * j + 1]);
            }
        }

        if (!more) break;
        tile += G;
        slab = nslab;
    }
}

extern "C" void kernel_launch(void* const* d_in, const int* in_sizes, int n_in,
                              void* d_out, int out_size) {
    const float* x = (const float*)d_in[0];
    const int B = in_sizes[0] / 64;
    const int ntiles = (B + 511) >> 9;

    cudaFuncSetAttribute(cvqnn_main,
                         cudaFuncAttributeMaxDynamicSharedMemorySize,
                         SMEM_BYTES);

    const int grid = (ntiles < 444) ? ntiles : 444;  // 148 SMs x 3 blocks
    cvqnn_main<<<grid, 128, SMEM_BYTES>>>(
        x, (float*)d_out, B, ntiles,
        (const float*)d_in[1], (const float*)d_in[2],
        (const float*)d_in[3], (const float*)d_in[4],
        (const float*)d_in[5], (const float*)d_in[6],
        (const float*)d_in[7], (const float*)d_in[8]);
}